// round 15
// baseline (speedup 1.0000x reference)
#include <cuda_runtime.h>

#define NN     8192
#define KP1    4096
#define KP2    2048
#define FF     32
#define FIN    16
#define MAXDEG 256
#define SUBMAX 192
#define CANDCAP 4096
#define CAND2   2048
#define FULLMASK 0xffffffffu

// ---------------- device scratch (static globals; no allocations) -------------
__device__ int    g_rowcnt[NN];
__device__ int    g_cols[NN * MAXDEG];       // padded CSR, rowstart = row*MAXDEG
__device__ int    g_subcnt[KP1];
__device__ int    g_subcols[KP1 * SUBMAX];   // rank-remapped sub CSR
__device__ float  g_dinv[NN];
__device__ float  g_dinvs[KP1];
__device__ float  g_G1[NN * FF];
__device__ float  g_X1[NN * FF];
__device__ float  g_G2[KP1 * FF];
__device__ float  g_X2[KP1 * FF];
__device__ float  g_G3[KP1 * FF];
__device__ float  g_X3[KP1 * FF];
__device__ float2 g_G4[NN];
__device__ float  g_score1[NN];
__device__ float  g_score2[KP1];
__device__ int    g_rank1[NN];
__device__ int    g_rank2[KP1];
__device__ int    g_idx1[KP1];
__device__ int    g_idx2[KP2];
__device__ unsigned g_hist1[256];            // chip-wide level-0 histograms
__device__ unsigned g_hist2[256];
__device__ unsigned g_histB[2][256];         // chip-wide level-1 (candidates)
__device__ unsigned g_poscnt[2];             // positions assigned so far
__device__ unsigned g_candcnt[2];            // boundary-bin candidate count
__device__ unsigned g_candk[2][CANDCAP];
__device__ int      g_candi[2][CANDCAP];

__device__ __forceinline__ unsigned flip_key(float f) {
    unsigned b = __float_as_uint(f);
    return (b & 0x80000000u) ? ~b : (b | 0x80000000u);
}

// ---------------- CSR build (mask-compressed) + dinv + G1 + init ---------------
__global__ void __launch_bounds__(256, 8)
k_csr(const float* __restrict__ A,
      const float* __restrict__ x,
      const float* __restrict__ W1) {
    int row = blockIdx.x;
    int t   = threadIdx.x;
    int lane = t & 31, wid = t >> 5;

    __shared__ float w1s[FIN * FF];
    __shared__ int wtot[8];
    __shared__ int wbase[8];
    __shared__ int stot;

    if (row == 0 && t < 256) {               // zero hists & counters (replayed)
        g_hist1[t] = 0; g_hist2[t] = 0;
        g_histB[0][t] = 0; g_histB[1][t] = 0;
        if (t < 2) { g_poscnt[t] = 0; g_candcnt[t] = 0; }
    }
    if (t < FIN * FF / 2) {            // 512 floats, 2 per thread
        w1s[t]       = W1[t];
        w1s[t + 256] = W1[t + 256];
    }

    // Load 8 float4 chunks; convert to a packed 32-bit nonzero mask immediately.
    const float4* ar = reinterpret_cast<const float4*>(A + (size_t)row * NN);
    unsigned m = 0;
#pragma unroll
    for (int k = 0; k < 8; k++) {
        float4 v = __ldcs(ar + k * 256 + t);
        unsigned mm = (unsigned)(v.x != 0.f) | ((unsigned)(v.y != 0.f) << 1) |
                      ((unsigned)(v.z != 0.f) << 2) | ((unsigned)(v.w != 0.f) << 3);
        m |= mm << (k * 4);
    }
    int c = __popc(m);

    int inc = c;
#pragma unroll
    for (int o = 1; o < 32; o <<= 1) {
        int y = __shfl_up_sync(FULLMASK, inc, o);
        if (lane >= o) inc += y;
    }
    if (lane == 31) wtot[wid] = inc;
    __syncthreads();
    if (t == 0) {
        int s = 0;
#pragma unroll
        for (int i = 0; i < 8; i++) { wbase[i] = s; s += wtot[i]; }
        stot = s;
        g_rowcnt[row] = (s < MAXDEG) ? s : MAXDEG;
        g_dinv[row]   = rsqrtf((float)s + 1.0f + 1e-10f);
    }
    __syncthreads();

    int off = wbase[wid] + inc - c;
    int* cp = g_cols + row * MAXDEG;
    unsigned mm = m;
    while (mm) {
        int b = __ffs(mm) - 1;
        mm &= mm - 1;
        int col = (((b >> 2) * 256 + t) << 2) + (b & 3);
        if (off < MAXDEG) cp[off] = col;
        off++;
    }

    // G1 row by warp 0
    if (wid == 0) {
        float d  = rsqrtf((float)stot + 1.0f + 1e-10f);
        float xv = (lane < FIN) ? x[row * FIN + lane] : 0.f;
        float acc = 0.f;
#pragma unroll
        for (int f = 0; f < FIN; f++) {
            float xf = __shfl_sync(FULLMASK, xv, f);
            acc += xf * w1s[f * FF + lane];
        }
        g_G1[row * FF + lane] = d * acc;
    }
}

// ---------------- main SpMM: X1 = relu(dinv*(A_hat @ G1)); score1 + hist -------
__global__ void k_spmm_main(const float* __restrict__ s1) {
    __shared__ float sv[FF];
    if (threadIdx.x < FF) sv[threadIdx.x] = s1[threadIdx.x];
    __syncthreads();
    int warp = (blockIdx.x * blockDim.x + threadIdx.x) >> 5;
    int lane = threadIdx.x & 31;
    if (warp >= NN) return;
    int g = lane >> 3, fo = lane & 7;
    int cnt = g_rowcnt[warp];
    const int* cp = g_cols + warp * MAXDEG;
    const float4* G1v = reinterpret_cast<const float4*>(g_G1);

    float4 acc = make_float4(0.f, 0.f, 0.f, 0.f);
    if (g == 0) acc = G1v[warp * 8 + fo];    // identity (+I) term

    for (int k0 = 0; k0 < cnt; k0 += 32) {
        int kc = k0 + lane;
        int mycol = (kc < cnt) ? cp[kc] : -1;
#pragma unroll
        for (int s = 0; s < 8; s++) {
            int c = __shfl_sync(FULLMASK, mycol, s * 4 + g);
            if (c >= 0) {
                float4 tv = G1v[c * 8 + fo];
                acc.x += tv.x; acc.y += tv.y; acc.z += tv.z; acc.w += tv.w;
            }
        }
    }
#pragma unroll
    for (int o = 8; o <= 16; o <<= 1) {
        acc.x += __shfl_xor_sync(FULLMASK, acc.x, o);
        acc.y += __shfl_xor_sync(FULLMASK, acc.y, o);
        acc.z += __shfl_xor_sync(FULLMASK, acc.z, o);
        acc.w += __shfl_xor_sync(FULLMASK, acc.w, o);
    }
    float d = g_dinv[warp];
    acc.x = fmaxf(d * acc.x, 0.f); acc.y = fmaxf(d * acc.y, 0.f);
    acc.z = fmaxf(d * acc.z, 0.f); acc.w = fmaxf(d * acc.w, 0.f);
    if (g == 0) reinterpret_cast<float4*>(g_X1)[warp * 8 + fo] = acc;

    float s = acc.x * sv[fo * 4 + 0] + acc.y * sv[fo * 4 + 1] +
              acc.z * sv[fo * 4 + 2] + acc.w * sv[fo * 4 + 3];
    s += __shfl_down_sync(FULLMASK, s, 4);
    s += __shfl_down_sync(FULLMASK, s, 2);
    s += __shfl_down_sync(FULLMASK, s, 1);
    if (lane == 0) {
        g_score1[warp] = s;
        atomicAdd(&g_hist1[flip_key(s) >> 24], 1u);   // no-return -> REDG
    }
}

// ---------------- shared helper: boundary bin from 256-bin histogram -----------
__device__ __forceinline__ void hist_suffix_scan(const unsigned* ghist, int K,
                                                 int* ssum, int* wagg,
                                                 int* sh_b, int t, int lane,
                                                 int wid) {
    int sval = 0;
    if (t < 256) {
        sval = (int)ghist[t];
#pragma unroll
        for (int o = 1; o < 32; o <<= 1) {
            int y = __shfl_down_sync(FULLMASK, sval, o);
            if (lane + o < 32) sval += y;
        }
        if (lane == 0) wagg[wid] = sval;
    }
    __syncthreads();
    if (t < 256) {
        int add = 0;
#pragma unroll
        for (int w = 0; w < 8; w++) if (w > wid) add += wagg[w];
        ssum[t] = sval + add;
        if (t == 0) ssum[256] = 0;
    }
    __syncthreads();
    if (t < 256 && ssum[t] >= K && ssum[t + 1] < K) *sh_b = t;
    __syncthreads();
}

// ---------------- classify: above-bin -> position; bin -> cand + histB ---------
__global__ void k_classify(int which) {
    const float*    scores = which ? g_score2 : g_score1;
    const unsigned* ghist  = which ? g_hist2  : g_hist1;
    int  n        = which ? KP1 : NN;
    int  K        = which ? KP2 : KP1;
    int* idx_out  = which ? g_idx2 : g_idx1;
    int* rank_out = which ? g_rank2 : g_rank1;
    unsigned* poscnt  = &g_poscnt[which];
    unsigned* candcnt = &g_candcnt[which];
    unsigned* candk   = g_candk[which];
    int*      candi   = g_candi[which];
    unsigned* histB   = g_histB[which];

    __shared__ int ssum[257];
    __shared__ int wagg[32];
    __shared__ int sh_b;
    __shared__ int wexc_a[32], wexc_c[32];
    __shared__ unsigned sh_base_a, sh_base_c;

    int t = threadIdx.x, lane = t & 31, wid = t >> 5;
    hist_suffix_scan(ghist, K, ssum, wagg, &sh_b, t, lane, wid);
    int b = sh_b;
    unsigned lt = (1u << lane) - 1u;

    int i = blockIdx.x * 1024 + t;
    unsigned u = (i < n) ? flip_key(scores[i]) : 0u;
    int hi = (int)(u >> 24);
    bool above = (i < n) && (hi > b);
    bool cand  = (i < n) && (hi == b);

    unsigned am = __ballot_sync(FULLMASK, above);
    unsigned cm = __ballot_sync(FULLMASK, cand);
    if (lane == 0) { wexc_a[wid] = __popc(am); wexc_c[wid] = __popc(cm); }
    __syncthreads();
    if (wid == 0) {
        int va = wexc_a[lane], vc = wexc_c[lane];
        int ia = va, ic = vc;
#pragma unroll
        for (int o = 1; o < 32; o <<= 1) {
            int ya = __shfl_up_sync(FULLMASK, ia, o);
            int yc = __shfl_up_sync(FULLMASK, ic, o);
            if (lane >= o) { ia += ya; ic += yc; }
        }
        wexc_a[lane] = ia - va;            // exclusive prefix within block
        wexc_c[lane] = ic - vc;
        if (lane == 31) {                  // one atomic per counter per block
            sh_base_a = ia ? atomicAdd(poscnt, (unsigned)ia) : 0u;
            sh_base_c = ic ? atomicAdd(candcnt, (unsigned)ic) : 0u;
        }
    }
    __syncthreads();

    if (above) {
        int pos = (int)(sh_base_a + wexc_a[wid] + __popc(am & lt));
        rank_out[i] = pos;
        idx_out[pos] = i;
    } else if (i < n) {
        rank_out[i] = -1;
        if (cand) {
            unsigned p = sh_base_c + wexc_c[wid] + __popc(cm & lt);
            if (p < CANDCAP) {
                candk[p] = u; candi[p] = i;
                atomicAdd(&histB[(u >> 16) & 255], 1u);   // level-1 histogram
            }
        }
    }
}

// ---------------- refine (1 block): precomputed level-1, no in-block hist ------
__global__ void k_refine(int which) {
    const unsigned* ghist  = which ? g_hist2  : g_hist1;
    const unsigned* ghistB = g_histB[which];
    int  K        = which ? KP2 : KP1;
    int* idx_out  = which ? g_idx2 : g_idx1;
    int* rank_out = which ? g_rank2 : g_rank1;
    unsigned* candk_g = g_candk[which];
    int*      candi_g = g_candi[which];

    __shared__ unsigned ck2[CAND2];      // 8 KB (level-1 boundary-bin survivors)
    __shared__ int      ci2[CAND2];      // 8 KB
    __shared__ int hist[257];
    __shared__ int ssum[257];
    __shared__ int wagg[32];
    __shared__ int sh_b, sh_cur, sh_pos;

    int t = threadIdx.x, lane = t & 31, wid = t >> 5;
    unsigned lt = (1u << lane) - 1u;

    // level-0: boundary bin, counts
    hist_suffix_scan(ghist, K, ssum, wagg, &sh_b, t, lane, wid);
    int b0 = sh_b;
    int above = ssum[b0 + 1];
    int need  = K - above;
    int c     = ssum[b0] - above;
    if (c > CANDCAP) c = CANDCAP;        // pathological mass-tie only
    __syncthreads();

    // level-1 (precomputed in classify): boundary sub-bin among candidates
    hist_suffix_scan(ghistB, need, ssum, wagg, &sh_b, t, lane, wid);
    int bb = sh_b;
    int above2 = ssum[bb + 1];
    int need2  = need - above2;
    int c2cnt  = ssum[bb] - above2;

    if (t == 0) { sh_pos = above; sh_cur = 0; }
    __syncthreads();

    // single pass over global candidates: assign hi-bin positions, compact ==bb
#pragma unroll
    for (int q = 0; q < 4; q++) {
        int m = t + q * 1024;
        bool valid = m < c;
        unsigned u = 0; int ii = 0; int bin = -1;
        if (valid) { u = candk_g[m]; ii = candi_g[m]; bin = (int)((u >> 16) & 255); }
        bool hi = valid && (bin > bb);
        bool eq = valid && (bin == bb);
        unsigned ma = __ballot_sync(FULLMASK, hi);
        if (ma) {
            int ldr = __ffs(ma) - 1;
            int base = 0;
            if (lane == ldr) base = atomicAdd(&sh_pos, __popc(ma));
            base = __shfl_sync(FULLMASK, base, ldr);
            if (hi) {
                int pos = base + __popc(ma & lt);
                rank_out[ii] = pos;
                idx_out[pos] = ii;
            }
        }
        unsigned me = __ballot_sync(FULLMASK, eq);
        if (me) {
            int ldr = __ffs(me) - 1;
            int base = 0;
            if (lane == ldr) base = atomicAdd(&sh_cur, __popc(me));
            base = __shfl_sync(FULLMASK, base, ldr);
            if (eq) {
                int p = base + __popc(me & lt);
                if (p < CAND2) { ck2[p] = u; ci2[p] = ii; }
            }
        }
    }
    __syncthreads();
    int c2 = (c2cnt < CAND2) ? c2cnt : CAND2;

    // rare fallback: refine ck2 at shift 8 then 0 (normally zero iterations)
    for (int shift = 8; shift >= 0 && c2 > need2 && c2 > 64; shift -= 8) {
        if (t < 256) hist[t] = 0;
        __syncthreads();
        for (int m = t; m < c2; m += 1024)
            atomicAdd(&hist[(ck2[m] >> shift) & 255], 1);
        __syncthreads();
        int sval = 0;
        if (t < 256) {
            sval = hist[t];
#pragma unroll
            for (int o = 1; o < 32; o <<= 1) {
                int y = __shfl_down_sync(FULLMASK, sval, o);
                if (lane + o < 32) sval += y;
            }
            if (lane == 0) wagg[wid] = sval;
        }
        __syncthreads();
        if (t < 256) {
            int add = 0;
#pragma unroll
            for (int w = 0; w < 8; w++) if (w > wid) add += wagg[w];
            ssum[t] = sval + add;
            if (t == 0) ssum[256] = 0;
        }
        __syncthreads();
        if (t < 256 && ssum[t] >= need2 && ssum[t + 1] < need2) sh_b = t;
        __syncthreads();
        int bb2 = sh_b;
        int newneed = need2 - ssum[bb2 + 1];
        int newc    = ssum[bb2] - ssum[bb2 + 1];

        unsigned kk[2]; int ii[2]; bool kp[2], sa[2];
#pragma unroll
        for (int q = 0; q < 2; q++) {
            kp[q] = false; sa[q] = false;
            int m = t + q * 1024;
            if (m < c2) {
                kk[q] = ck2[m]; ii[q] = ci2[m];
                int bin = (int)((kk[q] >> shift) & 255);
                sa[q] = (bin > bb2);
                kp[q] = (bin == bb2);
            }
        }
        if (t == 0) sh_cur = 0;
        __syncthreads();
#pragma unroll
        for (int q = 0; q < 2; q++) {
            unsigned ma = __ballot_sync(FULLMASK, sa[q]);
            if (ma) {
                int ldr = __ffs(ma) - 1;
                int base = 0;
                if (lane == ldr) base = atomicAdd(&sh_pos, __popc(ma));
                base = __shfl_sync(FULLMASK, base, ldr);
                if (sa[q]) {
                    int pos = base + __popc(ma & lt);
                    rank_out[ii[q]] = pos;
                    idx_out[pos] = ii[q];
                }
            }
            unsigned mk = __ballot_sync(FULLMASK, kp[q]);
            if (mk) {
                int ldr = __ffs(mk) - 1;
                int base = 0;
                if (lane == ldr) base = atomicAdd(&sh_cur, __popc(mk));
                base = __shfl_sync(FULLMASK, base, ldr);
                if (kp[q]) {
                    int p = base + __popc(mk & lt);
                    ck2[p] = kk[q]; ci2[p] = ii[q];
                }
            }
        }
        __syncthreads();
        c2 = newc; need2 = newneed;
    }

    int pbase = sh_pos;
    if (c2 == need2) {                   // exact split reached: bulk assign
        for (int m = t; m < c2; m += 1024) {
            int pos = pbase + m;
            rank_out[ci2[m]] = pos;
            idx_out[pos] = ci2[m];
        }
    } else if (c2 <= 64) {               // warp-0 exact ranking tail (no bars)
        if (wid == 0) {
            for (int m = lane; m < c2; m += 32) {
                unsigned km = ck2[m]; int im = ci2[m];
                int r = 0;
                for (int j = 0; j < c2; j++) {
                    unsigned kj = ck2[j];
                    r += (kj > km) || (kj == km && ci2[j] < im);
                }
                if (r < need2) {
                    int pos = pbase + r;
                    rank_out[im] = pos;
                    idx_out[pos] = im;
                }
            }
        }
    } else {                             // all-equal keys: lowest-index ranking
        for (int m = t; m < c2; m += 1024) {
            int mine = ci2[m], r = 0;
            for (int j = 0; j < c2; j++) r += (ci2[j] < mine);
            if (r < need2) {
                int pos = pbase + r;
                rank_out[mine] = pos;
                idx_out[pos] = mine;
            }
        }
    }
}

// ---------------- sub-CSR build + dinvs + G2 (fused, batched MLP) --------------
__global__ void k_sub(const float* __restrict__ W2) {
    __shared__ float w[FF * FF];
    for (int i = threadIdx.x; i < FF * FF; i += blockDim.x) w[i] = W2[i];
    __syncthreads();
    int r = (blockIdx.x * blockDim.x + threadIdx.x) >> 5;
    int lane = threadIdx.x & 31;
    if (r >= KP1) return;
    int i = g_idx1[r];
    int cnt = g_rowcnt[i];
    const int* cp = g_cols + i * MAXDEG;
    int* sp = g_subcols + r * SUBMAX;
    unsigned lt = (1u << lane) - 1u;
    int nch = (cnt + 31) >> 5;

    int col[8], rk[8];
#pragma unroll
    for (int c = 0; c < 8; c++) {
        int k = c * 32 + lane;
        col[c] = (c < nch && k < cnt) ? cp[k] : -1;
    }
#pragma unroll
    for (int c = 0; c < 8; c++)
        rk[c] = (col[c] >= 0) ? g_rank1[col[c]] : -1;

    int wcnt = 0;
#pragma unroll
    for (int c = 0; c < 8; c++) {
        if (c >= nch) break;
        int ok = (rk[c] >= 0);
        unsigned m = __ballot_sync(FULLMASK, ok);
        if (ok) { int p = wcnt + __popc(m & lt); if (p < SUBMAX) sp[p] = rk[c]; }
        wcnt += __popc(m);
    }
    float di = rsqrtf((float)wcnt + 1.0f + 1e-10f);
    if (lane == 0) {
        g_subcnt[r] = (wcnt < SUBMAX) ? wcnt : SUBMAX;
        g_dinvs[r]  = di;
    }
    float xv = g_X1[i * FF + lane];
    float acc = 0.f;
#pragma unroll
    for (int f = 0; f < FF; f++) {
        float xf = __shfl_sync(FULLMASK, xv, f);
        acc += xf * w[f * FF + lane];
    }
    g_G2[r * FF + lane] = di * acc;
}

// ---------------- subgraph SpMM (vectorized, pre-filtered sub-CSR) -------------
__global__ void k_spmm_sub(int phase, const float* __restrict__ svec) {
    __shared__ float sv[FF];
    if (phase == 0 && threadIdx.x < FF) sv[threadIdx.x] = svec[threadIdx.x];
    __syncthreads();
    const float4* Gv = reinterpret_cast<const float4*>(phase ? g_G3 : g_G2);
    float4*       Xv = reinterpret_cast<float4*>(phase ? g_X3 : g_X2);
    int r = (blockIdx.x * blockDim.x + threadIdx.x) >> 5;
    int lane = threadIdx.x & 31;
    if (r >= KP1) return;
    int g = lane >> 3, fo = lane & 7;
    int cnt = g_subcnt[r];
    const int* sp = g_subcols + r * SUBMAX;

    float4 acc = make_float4(0.f, 0.f, 0.f, 0.f);
    if (g == 0) acc = Gv[r * 8 + fo];
    for (int k0 = 0; k0 < cnt; k0 += 32) {
        int kc = k0 + lane;
        int mycol = (kc < cnt) ? sp[kc] : -1;
#pragma unroll
        for (int s = 0; s < 8; s++) {
            int c = __shfl_sync(FULLMASK, mycol, s * 4 + g);
            if (c >= 0) {
                float4 tv = Gv[c * 8 + fo];
                acc.x += tv.x; acc.y += tv.y; acc.z += tv.z; acc.w += tv.w;
            }
        }
    }
#pragma unroll
    for (int o = 8; o <= 16; o <<= 1) {
        acc.x += __shfl_xor_sync(FULLMASK, acc.x, o);
        acc.y += __shfl_xor_sync(FULLMASK, acc.y, o);
        acc.z += __shfl_xor_sync(FULLMASK, acc.z, o);
        acc.w += __shfl_xor_sync(FULLMASK, acc.w, o);
    }
    float d = g_dinvs[r];
    acc.x = fmaxf(d * acc.x, 0.f); acc.y = fmaxf(d * acc.y, 0.f);
    acc.z = fmaxf(d * acc.z, 0.f); acc.w = fmaxf(d * acc.w, 0.f);
    if (g == 0) Xv[r * 8 + fo] = acc;
    if (phase == 0) {
        float s = acc.x * sv[fo * 4 + 0] + acc.y * sv[fo * 4 + 1] +
                  acc.z * sv[fo * 4 + 2] + acc.w * sv[fo * 4 + 3];
        s += __shfl_down_sync(FULLMASK, s, 4);
        s += __shfl_down_sync(FULLMASK, s, 2);
        s += __shfl_down_sync(FULLMASK, s, 1);
        if (lane == 0) {
            g_score2[r] = s;
            atomicAdd(&g_hist2[flip_key(s) >> 24], 1u);
        }
    }
}

// ---------------- G3 = (rank2>=0) ? dinvs*(X2@W3) : 0 --------------------------
__global__ void k_g3(const float* __restrict__ W3) {
    __shared__ float w[FF * FF];
    for (int i = threadIdx.x; i < FF * FF; i += blockDim.x) w[i] = W3[i];
    __syncthreads();
    int r = (blockIdx.x * blockDim.x + threadIdx.x) >> 5;
    int lane = threadIdx.x & 31;
    if (r >= KP1) return;
    if (g_rank2[r] < 0) { g_G3[r * FF + lane] = 0.f; return; }
    float xv = g_X2[r * FF + lane];
    float acc = 0.f;
#pragma unroll
    for (int f = 0; f < FF; f++) {
        float xf = __shfl_sync(FULLMASK, xv, f);
        acc += xf * w[f * FF + lane];
    }
    g_G3[r * FF + lane] = g_dinvs[r] * acc;
}

// ---------------- G4 = dinv * (unpool1(X3) @ W4) -------------------------------
__global__ void k_g4(const float* __restrict__ W4) {
    __shared__ float w[FF * 2];
    for (int i = threadIdx.x; i < FF * 2; i += blockDim.x) w[i] = W4[i];
    __syncthreads();
    int i = blockIdx.x * blockDim.x + threadIdx.x;
    if (i >= NN) return;
    int rr = g_rank1[i];
    float h0 = 0.f, h1 = 0.f;
    if (rr >= 0) {
        const float4* xr = reinterpret_cast<const float4*>(g_X3 + rr * FF);
#pragma unroll
        for (int q = 0; q < 8; q++) {
            float4 xv = xr[q];
            h0 += xv.x * w[(q * 4 + 0) * 2] + xv.y * w[(q * 4 + 1) * 2] +
                  xv.z * w[(q * 4 + 2) * 2] + xv.w * w[(q * 4 + 3) * 2];
            h1 += xv.x * w[(q * 4 + 0) * 2 + 1] + xv.y * w[(q * 4 + 1) * 2 + 1] +
                  xv.z * w[(q * 4 + 2) * 2 + 1] + xv.w * w[(q * 4 + 3) * 2 + 1];
        }
    }
    float d = g_dinv[i];
    g_G4[i] = make_float2(d * h0, d * h1);
}

// ---------------- final SpMM (F=2) + normalization + softmax -------------------
__global__ void k_final(float* __restrict__ out) {
    int warp = (blockIdx.x * blockDim.x + threadIdx.x) >> 5;
    int lane = threadIdx.x & 31;
    if (warp >= NN) return;
    int cnt = g_rowcnt[warp];
    const int* cp = g_cols + warp * MAXDEG;
    float a0 = 0.f, a1 = 0.f;
    for (int k = lane; k < cnt; k += 32) {
        float2 gv = g_G4[cp[k]];
        a0 += gv.x; a1 += gv.y;
    }
#pragma unroll
    for (int o = 16; o > 0; o >>= 1) {
        a0 += __shfl_down_sync(FULLMASK, a0, o);
        a1 += __shfl_down_sync(FULLMASK, a1, o);
    }
    if (lane == 0) {
        float2 gs = g_G4[warp];
        float d = g_dinv[warp];
        float y0 = d * (a0 + gs.x);
        float y1 = d * (a1 + gs.y);
        float m = fmaxf(y0, y1);
        float e0 = expf(y0 - m);
        float e1 = expf(y1 - m);
        float inv = 1.0f / (e0 + e1);
        out[warp * 2 + 0] = e0 * inv;
        out[warp * 2 + 1] = e1 * inv;
    }
}

// ---------------- launcher ----------------------------------------------------
extern "C" void kernel_launch(void* const* d_in, const int* in_sizes, int n_in,
                              void* d_out, int out_size) {
    (void)in_sizes; (void)n_in; (void)out_size;
    const float* x  = (const float*)d_in[0];
    const float* a  = (const float*)d_in[1];
    const float* W1 = (const float*)d_in[2];
    const float* W2 = (const float*)d_in[3];
    const float* W3 = (const float*)d_in[4];
    const float* W4 = (const float*)d_in[5];
    const float* s1 = (const float*)d_in[6];
    const float* s2 = (const float*)d_in[7];
    float* out = (float*)d_out;

    k_csr<<<NN, 256>>>(a, x, W1);
    k_spmm_main<<<NN / 8, 256>>>(s1);
    k_classify<<<NN / 1024, 1024>>>(0);
    k_refine<<<1, 1024>>>(0);             // 4th launch -> profiled slot
    k_sub<<<KP1 / 8, 256>>>(W2);
    k_spmm_sub<<<KP1 / 8, 256>>>(0, s2);
    k_classify<<<KP1 / 1024, 1024>>>(1);
    k_refine<<<1, 1024>>>(1);
    k_g3<<<KP1 / 8, 256>>>(W3);
    k_spmm_sub<<<KP1 / 8, 256>>>(1, nullptr);
    k_g4<<<NN / 256, 256>>>(W4);
    k_final<<<NN / 8, 256>>>(out);
}

// round 16
// speedup vs baseline: 1.2741x; 1.2741x over previous
#include <cuda_runtime.h>

#define NN     8192
#define KP1    4096
#define KP2    2048
#define FF     32
#define FIN    16
#define MAXDEG 256
#define SUBMAX 192
#define CANDCAP 4096
#define FULLMASK 0xffffffffu

// ---------------- device scratch (static globals; no allocations) -------------
__device__ int    g_rowcnt[NN];
__device__ int    g_cols[NN * MAXDEG];       // padded CSR, rowstart = row*MAXDEG
__device__ int    g_subcnt[KP1];
__device__ int    g_subcols[KP1 * SUBMAX];   // rank-remapped sub CSR
__device__ float  g_dinv[NN];
__device__ float  g_dinvs[KP1];
__device__ float  g_G1[NN * FF];
__device__ float  g_X1[NN * FF];
__device__ float  g_G2[KP1 * FF];
__device__ float  g_X2[KP1 * FF];
__device__ float  g_G3[KP1 * FF];
__device__ float  g_X3[KP1 * FF];
__device__ float2 g_G4[NN];
__device__ float  g_score1[NN];
__device__ float  g_score2[KP1];
__device__ int    g_rank1[NN];
__device__ int    g_rank2[KP1];
__device__ int    g_idx1[KP1];
__device__ int    g_idx2[KP2];
__device__ unsigned g_hist1[256];            // chip-wide score histograms
__device__ unsigned g_hist2[256];
__device__ unsigned g_poscnt[2];             // positions assigned so far
__device__ unsigned g_candcnt[2];            // boundary-bin candidate count
__device__ unsigned g_candk[2][CANDCAP];
__device__ int      g_candi[2][CANDCAP];

__device__ __forceinline__ unsigned flip_key(float f) {
    unsigned b = __float_as_uint(f);
    return (b & 0x80000000u) ? ~b : (b | 0x80000000u);
}

// ---------------- CSR build (mask-compressed) + dinv + G1 + init ---------------
__global__ void __launch_bounds__(256, 8)
k_csr(const float* __restrict__ A,
      const float* __restrict__ x,
      const float* __restrict__ W1) {
    int row = blockIdx.x;
    int t   = threadIdx.x;
    int lane = t & 31, wid = t >> 5;

    __shared__ float w1s[FIN * FF];
    __shared__ int wtot[8];
    __shared__ int wbase[8];
    __shared__ int stot;

    if (row == 0 && t < 256) {               // zero hists & counters (replayed)
        g_hist1[t] = 0; g_hist2[t] = 0;
        if (t < 2) { g_poscnt[t] = 0; g_candcnt[t] = 0; }
    }
    if (t < FIN * FF / 2) {            // 512 floats, 2 per thread
        w1s[t]       = W1[t];
        w1s[t + 256] = W1[t + 256];
    }

    // Load 8 float4 chunks; convert to a packed 32-bit nonzero mask immediately.
    const float4* ar = reinterpret_cast<const float4*>(A + (size_t)row * NN);
    unsigned m = 0;
#pragma unroll
    for (int k = 0; k < 8; k++) {
        float4 v = __ldcs(ar + k * 256 + t);
        unsigned mm = (unsigned)(v.x != 0.f) | ((unsigned)(v.y != 0.f) << 1) |
                      ((unsigned)(v.z != 0.f) << 2) | ((unsigned)(v.w != 0.f) << 3);
        m |= mm << (k * 4);
    }
    int c = __popc(m);

    int inc = c;
#pragma unroll
    for (int o = 1; o < 32; o <<= 1) {
        int y = __shfl_up_sync(FULLMASK, inc, o);
        if (lane >= o) inc += y;
    }
    if (lane == 31) wtot[wid] = inc;
    __syncthreads();
    if (t == 0) {
        int s = 0;
#pragma unroll
        for (int i = 0; i < 8; i++) { wbase[i] = s; s += wtot[i]; }
        stot = s;
        g_rowcnt[row] = (s < MAXDEG) ? s : MAXDEG;
        g_dinv[row]   = rsqrtf((float)s + 1.0f + 1e-10f);
    }
    __syncthreads();

    int off = wbase[wid] + inc - c;
    int* cp = g_cols + row * MAXDEG;
    unsigned mm = m;
    while (mm) {
        int b = __ffs(mm) - 1;
        mm &= mm - 1;
        int col = (((b >> 2) * 256 + t) << 2) + (b & 3);
        if (off < MAXDEG) cp[off] = col;
        off++;
    }

    // G1 row by warp 0
    if (wid == 0) {
        float d  = rsqrtf((float)stot + 1.0f + 1e-10f);
        float xv = (lane < FIN) ? x[row * FIN + lane] : 0.f;
        float acc = 0.f;
#pragma unroll
        for (int f = 0; f < FIN; f++) {
            float xf = __shfl_sync(FULLMASK, xv, f);
            acc += xf * w1s[f * FF + lane];
        }
        g_G1[row * FF + lane] = d * acc;
    }
}

// ---------------- main SpMM: X1 = relu(dinv*(A_hat @ G1)); score1 + hist -------
__global__ void k_spmm_main(const float* __restrict__ s1) {
    __shared__ float sv[FF];
    if (threadIdx.x < FF) sv[threadIdx.x] = s1[threadIdx.x];
    __syncthreads();
    int warp = (blockIdx.x * blockDim.x + threadIdx.x) >> 5;
    int lane = threadIdx.x & 31;
    if (warp >= NN) return;
    int g = lane >> 3, fo = lane & 7;
    int cnt = g_rowcnt[warp];
    const int* cp = g_cols + warp * MAXDEG;
    const float4* G1v = reinterpret_cast<const float4*>(g_G1);

    float4 acc = make_float4(0.f, 0.f, 0.f, 0.f);
    if (g == 0) acc = G1v[warp * 8 + fo];    // identity (+I) term

    for (int k0 = 0; k0 < cnt; k0 += 32) {
        int kc = k0 + lane;
        int mycol = (kc < cnt) ? cp[kc] : -1;
#pragma unroll
        for (int s = 0; s < 8; s++) {
            int c = __shfl_sync(FULLMASK, mycol, s * 4 + g);
            if (c >= 0) {
                float4 tv = G1v[c * 8 + fo];
                acc.x += tv.x; acc.y += tv.y; acc.z += tv.z; acc.w += tv.w;
            }
        }
    }
#pragma unroll
    for (int o = 8; o <= 16; o <<= 1) {
        acc.x += __shfl_xor_sync(FULLMASK, acc.x, o);
        acc.y += __shfl_xor_sync(FULLMASK, acc.y, o);
        acc.z += __shfl_xor_sync(FULLMASK, acc.z, o);
        acc.w += __shfl_xor_sync(FULLMASK, acc.w, o);
    }
    float d = g_dinv[warp];
    acc.x = fmaxf(d * acc.x, 0.f); acc.y = fmaxf(d * acc.y, 0.f);
    acc.z = fmaxf(d * acc.z, 0.f); acc.w = fmaxf(d * acc.w, 0.f);
    if (g == 0) reinterpret_cast<float4*>(g_X1)[warp * 8 + fo] = acc;

    float s = acc.x * sv[fo * 4 + 0] + acc.y * sv[fo * 4 + 1] +
              acc.z * sv[fo * 4 + 2] + acc.w * sv[fo * 4 + 3];
    s += __shfl_down_sync(FULLMASK, s, 4);
    s += __shfl_down_sync(FULLMASK, s, 2);
    s += __shfl_down_sync(FULLMASK, s, 1);
    if (lane == 0) {
        g_score1[warp] = s;
        atomicAdd(&g_hist1[flip_key(s) >> 24], 1u);   // no-return -> REDG
    }
}

// ---------------- shared helper: boundary bin from 256-bin histogram -----------
__device__ __forceinline__ void hist_suffix_scan(const unsigned* ghist, int K,
                                                 int* ssum, int* wagg,
                                                 int* sh_b, int t, int lane,
                                                 int wid) {
    int sval = 0;
    if (t < 256) {
        sval = (int)ghist[t];
#pragma unroll
        for (int o = 1; o < 32; o <<= 1) {
            int y = __shfl_down_sync(FULLMASK, sval, o);
            if (lane + o < 32) sval += y;
        }
        if (lane == 0) wagg[wid] = sval;
    }
    __syncthreads();
    if (t < 256) {
        int add = 0;
#pragma unroll
        for (int w = 0; w < 8; w++) if (w > wid) add += wagg[w];
        ssum[t] = sval + add;
        if (t == 0) ssum[256] = 0;
    }
    __syncthreads();
    if (t < 256 && ssum[t] >= K && ssum[t + 1] < K) *sh_b = t;
    __syncthreads();
}

// ---------------- classify (multi-block, block-aggregated atomics) -------------
__global__ void k_classify(int which) {
    const float*    scores = which ? g_score2 : g_score1;
    const unsigned* ghist  = which ? g_hist2  : g_hist1;
    int  n        = which ? KP1 : NN;
    int  K        = which ? KP2 : KP1;
    int* idx_out  = which ? g_idx2 : g_idx1;
    int* rank_out = which ? g_rank2 : g_rank1;
    unsigned* poscnt  = &g_poscnt[which];
    unsigned* candcnt = &g_candcnt[which];
    unsigned* candk   = g_candk[which];
    int*      candi   = g_candi[which];

    __shared__ int ssum[257];
    __shared__ int wagg[32];
    __shared__ int sh_b;
    __shared__ int wexc_a[32], wexc_c[32];
    __shared__ unsigned sh_base_a, sh_base_c;

    int t = threadIdx.x, lane = t & 31, wid = t >> 5;
    hist_suffix_scan(ghist, K, ssum, wagg, &sh_b, t, lane, wid);
    int b = sh_b;
    unsigned lt = (1u << lane) - 1u;

    int i = blockIdx.x * 1024 + t;
    unsigned u = (i < n) ? flip_key(scores[i]) : 0u;
    int hi = (int)(u >> 24);
    bool above = (i < n) && (hi > b);
    bool cand  = (i < n) && (hi == b);

    unsigned am = __ballot_sync(FULLMASK, above);
    unsigned cm = __ballot_sync(FULLMASK, cand);
    if (lane == 0) { wexc_a[wid] = __popc(am); wexc_c[wid] = __popc(cm); }
    __syncthreads();
    if (wid == 0) {
        int va = wexc_a[lane], vc = wexc_c[lane];
        int ia = va, ic = vc;
#pragma unroll
        for (int o = 1; o < 32; o <<= 1) {
            int ya = __shfl_up_sync(FULLMASK, ia, o);
            int yc = __shfl_up_sync(FULLMASK, ic, o);
            if (lane >= o) { ia += ya; ic += yc; }
        }
        wexc_a[lane] = ia - va;            // exclusive prefix within block
        wexc_c[lane] = ic - vc;
        if (lane == 31) {                  // one atomic per counter per block
            sh_base_a = ia ? atomicAdd(poscnt, (unsigned)ia) : 0u;
            sh_base_c = ic ? atomicAdd(candcnt, (unsigned)ic) : 0u;
        }
    }
    __syncthreads();

    if (above) {
        int pos = (int)(sh_base_a + wexc_a[wid] + __popc(am & lt));
        rank_out[i] = pos;
        idx_out[pos] = i;
    } else if (i < n) {
        rank_out[i] = -1;
        if (cand) {
            unsigned p = sh_base_c + wexc_c[wid] + __popc(cm & lt);
            if (p < CANDCAP) { candk[p] = u; candi[p] = i; }
        }
    }
}

// ---------------- refine (1 block): full-block level (packed scan) + tail ------
__global__ void k_refine(int which) {
    const unsigned* ghist  = which ? g_hist2  : g_hist1;
    int  K        = which ? KP2 : KP1;
    int* idx_out  = which ? g_idx2 : g_idx1;
    int* rank_out = which ? g_rank2 : g_rank1;
    unsigned* candk_g = g_candk[which];
    int*      candi_g = g_candi[which];

    __shared__ unsigned ck[CANDCAP];     // 16 KB
    __shared__ int      ci[CANDCAP];     // 16 KB
    __shared__ int hist[257];
    __shared__ int ssum[257];
    __shared__ int wagg[32];
    __shared__ int wexc[32];
    __shared__ int sh_b, sh_pos, sh_tot;

    int t = threadIdx.x, lane = t & 31, wid = t >> 5;
    hist_suffix_scan(ghist, K, ssum, wagg, &sh_b, t, lane, wid);
    int b = sh_b;
    int above = ssum[b + 1];
    int need  = K - above;
    int c     = ssum[b] - above;
    if (c > CANDCAP) c = CANDCAP;        // pathological mass-tie only

    for (int m = t; m < c; m += 1024) { ck[m] = candk_g[m]; ci[m] = candi_g[m]; }
    if (t == 0) sh_pos = above;          // next position to hand out
    __syncthreads();

    int shift = 24;
    while (shift > 0 && c > need && c > 64) {
        shift -= 8;
        if (t < 256) hist[t] = 0;
        __syncthreads();
        for (int m = t; m < c; m += 1024)
            atomicAdd(&hist[(ck[m] >> shift) & 255], 1);
        __syncthreads();
        int sval = 0;
        if (t < 256) {
            sval = hist[t];
#pragma unroll
            for (int o = 1; o < 32; o <<= 1) {
                int y = __shfl_down_sync(FULLMASK, sval, o);
                if (lane + o < 32) sval += y;
            }
            if (lane == 0) wagg[wid] = sval;
        }
        __syncthreads();
        if (t < 256) {
            int add = 0;
#pragma unroll
            for (int w = 0; w < 8; w++) if (w > wid) add += wagg[w];
            ssum[t] = sval + add;
            if (t == 0) ssum[256] = 0;
        }
        __syncthreads();
        if (t < 256 && ssum[t] >= need && ssum[t + 1] < need) sh_b = t;
        __syncthreads();
        int bb = sh_b;
        int newneed = need - ssum[bb + 1];
        int newc    = ssum[bb] - ssum[bb + 1];
        int pbase0  = sh_pos;

        // gather all candidates to registers before any rewrite
        unsigned kk[4]; int ii[4]; bool kp[4], sa[4];
        int nsa = 0, nkp = 0;
#pragma unroll
        for (int q = 0; q < 4; q++) {
            kp[q] = false; sa[q] = false;
            int m = t + q * 1024;
            if (m < c) {
                kk[q] = ck[m]; ii[q] = ci[m];
                int bin = (int)((kk[q] >> shift) & 255);
                sa[q] = (bin > bb);      // selected NOW (above refined boundary)
                kp[q] = (bin == bb);     // survives to next level
                nsa += sa[q]; nkp += kp[q];
            }
        }
        __syncthreads();                 // reads done before compaction writes

        // ONE packed block scan (sa<<16 | kp); no shared atomics at all
        int packed = (nsa << 16) | nkp;
        int s = packed;
#pragma unroll
        for (int o = 1; o < 32; o <<= 1) {
            int y = __shfl_up_sync(FULLMASK, s, o);
            if (lane >= o) s += y;
        }
        if (lane == 31) wagg[wid] = s;
        __syncthreads();
        if (wid == 0) {
            int w = wagg[lane];
#pragma unroll
            for (int o = 1; o < 32; o <<= 1) {
                int y = __shfl_up_sync(FULLMASK, w, o);
                if (lane >= o) w += y;
            }
            wexc[lane] = w;
            if (lane == 31) sh_tot = w;
        }
        __syncthreads();
        int excl = s - packed + (wid ? wexc[wid - 1] : 0);
        int sab = pbase0 + (excl >> 16);
        int kpb = excl & 0xffff;
#pragma unroll
        for (int q = 0; q < 4; q++) {
            if (sa[q]) {
                rank_out[ii[q]] = sab;
                idx_out[sab] = ii[q];
                sab++;
            }
            if (kp[q]) { ck[kpb] = kk[q]; ci[kpb] = ii[q]; kpb++; }
        }
        __syncthreads();
        if (t == 0) sh_pos = pbase0 + (sh_tot >> 16);
        __syncthreads();
        c = newc; need = newneed;
    }

    int pbase = sh_pos;
    if (c == need) {                     // exact split reached: bulk assign
        for (int m = t; m < c; m += 1024) {
            int pos = pbase + m;
            rank_out[ci[m]] = pos;
            idx_out[pos] = ci[m];
        }
    } else if (c <= 64) {                // warp-0 exact ranking tail (no bars)
        if (wid == 0) {
            for (int m = lane; m < c; m += 32) {
                unsigned km = ck[m]; int im = ci[m];
                int r = 0;
                for (int j = 0; j < c; j++) {
                    unsigned kj = ck[j];
                    r += (kj > km) || (kj == km && ci[j] < im);
                }
                if (r < need) {
                    int pos = pbase + r;
                    rank_out[im] = pos;
                    idx_out[pos] = im;
                }
            }
        }
    } else {                             // shift==0 mass ties: index ranking
        for (int m = t; m < c; m += 1024) {
            int mine = ci[m], r = 0;
            for (int j = 0; j < c; j++) r += (ci[j] < mine);
            if (r < need) {
                int pos = pbase + r;
                rank_out[mine] = pos;
                idx_out[pos] = mine;
            }
        }
    }
}

// ---------------- sub-CSR build + dinvs + G2 (fused, batched MLP) --------------
__global__ void k_sub(const float* __restrict__ W2) {
    __shared__ float w[FF * FF];
    for (int i = threadIdx.x; i < FF * FF; i += blockDim.x) w[i] = W2[i];
    __syncthreads();
    int r = (blockIdx.x * blockDim.x + threadIdx.x) >> 5;
    int lane = threadIdx.x & 31;
    if (r >= KP1) return;
    int i = g_idx1[r];
    int cnt = g_rowcnt[i];
    const int* cp = g_cols + i * MAXDEG;
    int* sp = g_subcols + r * SUBMAX;
    unsigned lt = (1u << lane) - 1u;
    int nch = (cnt + 31) >> 5;

    int col[8], rk[8];
#pragma unroll
    for (int c = 0; c < 8; c++) {
        int k = c * 32 + lane;
        col[c] = (c < nch && k < cnt) ? cp[k] : -1;
    }
#pragma unroll
    for (int c = 0; c < 8; c++)
        rk[c] = (col[c] >= 0) ? g_rank1[col[c]] : -1;

    int wcnt = 0;
#pragma unroll
    for (int c = 0; c < 8; c++) {
        if (c >= nch) break;
        int ok = (rk[c] >= 0);
        unsigned m = __ballot_sync(FULLMASK, ok);
        if (ok) { int p = wcnt + __popc(m & lt); if (p < SUBMAX) sp[p] = rk[c]; }
        wcnt += __popc(m);
    }
    float di = rsqrtf((float)wcnt + 1.0f + 1e-10f);
    if (lane == 0) {
        g_subcnt[r] = (wcnt < SUBMAX) ? wcnt : SUBMAX;
        g_dinvs[r]  = di;
    }
    float xv = g_X1[i * FF + lane];
    float acc = 0.f;
#pragma unroll
    for (int f = 0; f < FF; f++) {
        float xf = __shfl_sync(FULLMASK, xv, f);
        acc += xf * w[f * FF + lane];
    }
    g_G2[r * FF + lane] = di * acc;
}

// ---------------- subgraph SpMM (vectorized, pre-filtered sub-CSR) -------------
__global__ void k_spmm_sub(int phase, const float* __restrict__ svec) {
    __shared__ float sv[FF];
    if (phase == 0 && threadIdx.x < FF) sv[threadIdx.x] = svec[threadIdx.x];
    __syncthreads();
    const float4* Gv = reinterpret_cast<const float4*>(phase ? g_G3 : g_G2);
    float4*       Xv = reinterpret_cast<float4*>(phase ? g_X3 : g_X2);
    int r = (blockIdx.x * blockDim.x + threadIdx.x) >> 5;
    int lane = threadIdx.x & 31;
    if (r >= KP1) return;
    int g = lane >> 3, fo = lane & 7;
    int cnt = g_subcnt[r];
    const int* sp = g_subcols + r * SUBMAX;

    float4 acc = make_float4(0.f, 0.f, 0.f, 0.f);
    if (g == 0) acc = Gv[r * 8 + fo];
    for (int k0 = 0; k0 < cnt; k0 += 32) {
        int kc = k0 + lane;
        int mycol = (kc < cnt) ? sp[kc] : -1;
#pragma unroll
        for (int s = 0; s < 8; s++) {
            int c = __shfl_sync(FULLMASK, mycol, s * 4 + g);
            if (c >= 0) {
                float4 tv = Gv[c * 8 + fo];
                acc.x += tv.x; acc.y += tv.y; acc.z += tv.z; acc.w += tv.w;
            }
        }
    }
#pragma unroll
    for (int o = 8; o <= 16; o <<= 1) {
        acc.x += __shfl_xor_sync(FULLMASK, acc.x, o);
        acc.y += __shfl_xor_sync(FULLMASK, acc.y, o);
        acc.z += __shfl_xor_sync(FULLMASK, acc.z, o);
        acc.w += __shfl_xor_sync(FULLMASK, acc.w, o);
    }
    float d = g_dinvs[r];
    acc.x = fmaxf(d * acc.x, 0.f); acc.y = fmaxf(d * acc.y, 0.f);
    acc.z = fmaxf(d * acc.z, 0.f); acc.w = fmaxf(d * acc.w, 0.f);
    if (g == 0) Xv[r * 8 + fo] = acc;
    if (phase == 0) {
        float s = acc.x * sv[fo * 4 + 0] + acc.y * sv[fo * 4 + 1] +
                  acc.z * sv[fo * 4 + 2] + acc.w * sv[fo * 4 + 3];
        s += __shfl_down_sync(FULLMASK, s, 4);
        s += __shfl_down_sync(FULLMASK, s, 2);
        s += __shfl_down_sync(FULLMASK, s, 1);
        if (lane == 0) {
            g_score2[r] = s;
            atomicAdd(&g_hist2[flip_key(s) >> 24], 1u);
        }
    }
}

// ---------------- G3 = (rank2>=0) ? dinvs*(X2@W3) : 0 --------------------------
__global__ void k_g3(const float* __restrict__ W3) {
    __shared__ float w[FF * FF];
    for (int i = threadIdx.x; i < FF * FF; i += blockDim.x) w[i] = W3[i];
    __syncthreads();
    int r = (blockIdx.x * blockDim.x + threadIdx.x) >> 5;
    int lane = threadIdx.x & 31;
    if (r >= KP1) return;
    if (g_rank2[r] < 0) { g_G3[r * FF + lane] = 0.f; return; }
    float xv = g_X2[r * FF + lane];
    float acc = 0.f;
#pragma unroll
    for (int f = 0; f < FF; f++) {
        float xf = __shfl_sync(FULLMASK, xv, f);
        acc += xf * w[f * FF + lane];
    }
    g_G3[r * FF + lane] = g_dinvs[r] * acc;
}

// ---------------- G4 = dinv * (unpool1(X3) @ W4) -------------------------------
__global__ void k_g4(const float* __restrict__ W4) {
    __shared__ float w[FF * 2];
    for (int i = threadIdx.x; i < FF * 2; i += blockDim.x) w[i] = W4[i];
    __syncthreads();
    int i = blockIdx.x * blockDim.x + threadIdx.x;
    if (i >= NN) return;
    int rr = g_rank1[i];
    float h0 = 0.f, h1 = 0.f;
    if (rr >= 0) {
        const float4* xr = reinterpret_cast<const float4*>(g_X3 + rr * FF);
#pragma unroll
        for (int q = 0; q < 8; q++) {
            float4 xv = xr[q];
            h0 += xv.x * w[(q * 4 + 0) * 2] + xv.y * w[(q * 4 + 1) * 2] +
                  xv.z * w[(q * 4 + 2) * 2] + xv.w * w[(q * 4 + 3) * 2];
            h1 += xv.x * w[(q * 4 + 0) * 2 + 1] + xv.y * w[(q * 4 + 1) * 2 + 1] +
                  xv.z * w[(q * 4 + 2) * 2 + 1] + xv.w * w[(q * 4 + 3) * 2 + 1];
        }
    }
    float d = g_dinv[i];
    g_G4[i] = make_float2(d * h0, d * h1);
}

// ---------------- final SpMM (F=2) + normalization + softmax -------------------
__global__ void k_final(float* __restrict__ out) {
    int warp = (blockIdx.x * blockDim.x + threadIdx.x) >> 5;
    int lane = threadIdx.x & 31;
    if (warp >= NN) return;
    int cnt = g_rowcnt[warp];
    const int* cp = g_cols + warp * MAXDEG;
    float a0 = 0.f, a1 = 0.f;
    for (int k = lane; k < cnt; k += 32) {
        float2 gv = g_G4[cp[k]];
        a0 += gv.x; a1 += gv.y;
    }
#pragma unroll
    for (int o = 16; o > 0; o >>= 1) {
        a0 += __shfl_down_sync(FULLMASK, a0, o);
        a1 += __shfl_down_sync(FULLMASK, a1, o);
    }
    if (lane == 0) {
        float2 gs = g_G4[warp];
        float d = g_dinv[warp];
        float y0 = d * (a0 + gs.x);
        float y1 = d * (a1 + gs.y);
        float m = fmaxf(y0, y1);
        float e0 = expf(y0 - m);
        float e1 = expf(y1 - m);
        float inv = 1.0f / (e0 + e1);
        out[warp * 2 + 0] = e0 * inv;
        out[warp * 2 + 1] = e1 * inv;
    }
}

// ---------------- launcher ----------------------------------------------------
extern "C" void kernel_launch(void* const* d_in, const int* in_sizes, int n_in,
                              void* d_out, int out_size) {
    (void)in_sizes; (void)n_in; (void)out_size;
    const float* x  = (const float*)d_in[0];
    const float* a  = (const float*)d_in[1];
    const float* W1 = (const float*)d_in[2];
    const float* W2 = (const float*)d_in[3];
    const float* W3 = (const float*)d_in[4];
    const float* W4 = (const float*)d_in[5];
    const float* s1 = (const float*)d_in[6];
    const float* s2 = (const float*)d_in[7];
    float* out = (float*)d_out;

    k_csr<<<NN, 256>>>(a, x, W1);
    k_spmm_main<<<NN / 8, 256>>>(s1);
    k_classify<<<NN / 1024, 1024>>>(0);
    k_refine<<<1, 1024>>>(0);             // 4th launch -> profiled slot
    k_sub<<<KP1 / 8, 256>>>(W2);
    k_spmm_sub<<<KP1 / 8, 256>>>(0, s2);
    k_classify<<<KP1 / 1024, 1024>>>(1);
    k_refine<<<1, 1024>>>(1);
    k_g3<<<KP1 / 8, 256>>>(W3);
    k_spmm_sub<<<KP1 / 8, 256>>>(1, nullptr);
    k_g4<<<NN / 256, 256>>>(W4);
    k_final<<<NN / 8, 256>>>(out);
}